// round 8
// baseline (speedup 1.0000x reference)
#include <cuda_runtime.h>
#include <cuda_fp16.h>
#include <cuda_bf16.h>
#include <cstdint>

#define BN 512   // batches
#define KN 128   // points per batch
#define DN 512   // feature dim

// Scratch (static device allocations allowed)
__device__ __half  g_cost[(size_t)BN * KN * KN];   // 16.8 MB, cost = -x.y (fp16)
__device__ int     g_perm[BN * KN];
__device__ double  g_partial[BN];

// ---------------------------------------------------------------------------
// helpers
// ---------------------------------------------------------------------------
__device__ __forceinline__ uint32_t smem_u32(const void* p) {
    return (uint32_t)__cvta_generic_to_shared(p);
}
__device__ __forceinline__ void ldsm_x4(uint32_t& r0, uint32_t& r1,
                                        uint32_t& r2, uint32_t& r3, uint32_t addr) {
    asm volatile("ldmatrix.sync.aligned.m8n8.x4.shared.b16 {%0,%1,%2,%3}, [%4];"
                 : "=r"(r0), "=r"(r1), "=r"(r2), "=r"(r3) : "r"(addr));
}
__device__ __forceinline__ void mma_bf16(float& c0, float& c1, float& c2, float& c3,
                                         uint32_t a0, uint32_t a1, uint32_t a2, uint32_t a3,
                                         uint32_t b0, uint32_t b1) {
    asm volatile("mma.sync.aligned.m16n8k16.row.col.f32.bf16.bf16.f32 "
                 "{%0,%1,%2,%3}, {%4,%5,%6,%7}, {%8,%9}, {%0,%1,%2,%3};"
                 : "+f"(c0), "+f"(c1), "+f"(c2), "+f"(c3)
                 : "r"(a0), "r"(a1), "r"(a2), "r"(a3), "r"(b0), "r"(b1));
}
__device__ __forceinline__ unsigned redux_min_u32(unsigned v) {
    unsigned r;
    asm("redux.sync.min.u32 %0, %1, 0xffffffff;" : "=r"(r) : "r"(v));
    return r;
}
__device__ __forceinline__ unsigned ordkey(float f) {
    unsigned u = __float_as_uint(f);
    return (u & 0x80000000u) ? ~u : (u | 0x80000000u);
}
__device__ __forceinline__ float unordkey(unsigned k) {
    unsigned u = (k & 0x80000000u) ? (k & 0x7fffffffu) : ~k;
    return __uint_as_float(u);
}

// ---------------------------------------------------------------------------
// Kernel 1: C[b][i][j] = -(X[b,i,:] . Y[b,j,:]), bf16 MMA, fp16 output.
// One CTA per batch. 256 thr = 8 warps in a 2(M) x 4(N) grid; warp tile 64x32.
// ---------------------------------------------------------------------------
__device__ __forceinline__ int chunk_off(int row, int c) {   // in 16B units
    return row * 8 + (c ^ (row & 7));
}

__global__ __launch_bounds__(256) void cost_kernel(const float* __restrict__ X,
                                                   const float* __restrict__ Y) {
    __shared__ uint4 Xs[1024];   // 16 KB: 128 rows x 8 chunks
    __shared__ uint4 Ys[1024];   // 16 KB

    const int b   = blockIdx.x;
    const int tid = threadIdx.x;
    const int w    = tid >> 5;
    const int lane = tid & 31;
    const int wm = w >> 2;       // 0..1  -> m base = wm*64
    const int wn = w & 3;        // 0..3  -> n base = wn*32

    const float* xb = X + (size_t)b * KN * DN;
    const float* yb = Y + (size_t)b * KN * DN;

    float acc[4][4][4];
#pragma unroll
    for (int mt = 0; mt < 4; mt++)
#pragma unroll
        for (int nt = 0; nt < 4; nt++)
#pragma unroll
            for (int q = 0; q < 4; q++) acc[mt][nt][q] = 0.f;

    const uint32_t xs_base = smem_u32(Xs);
    const uint32_t ys_base = smem_u32(Ys);

    for (int kb = 0; kb < 8; kb++) {     // K blocks of 64
#pragma unroll
        for (int qi = 0; qi < 4; qi++) {
            int q   = tid + 256 * qi;    // 0..1023
            int row = q >> 3;
            int c   = q & 7;
            const float* sx = xb + row * DN + kb * 64 + c * 8;
            const float* sy = yb + row * DN + kb * 64 + c * 8;
            float4 f0 = *(const float4*)sx;
            float4 f1 = *(const float4*)(sx + 4);
            uint4 pk;
            { __nv_bfloat162 t0 = __floats2bfloat162_rn(f0.x, f0.y); pk.x = *(uint32_t*)&t0; }
            { __nv_bfloat162 t1 = __floats2bfloat162_rn(f0.z, f0.w); pk.y = *(uint32_t*)&t1; }
            { __nv_bfloat162 t2 = __floats2bfloat162_rn(f1.x, f1.y); pk.z = *(uint32_t*)&t2; }
            { __nv_bfloat162 t3 = __floats2bfloat162_rn(f1.z, f1.w); pk.w = *(uint32_t*)&t3; }
            Xs[chunk_off(row, c)] = pk;
            float4 g0 = *(const float4*)sy;
            float4 g1 = *(const float4*)(sy + 4);
            { __nv_bfloat162 t0 = __floats2bfloat162_rn(g0.x, g0.y); pk.x = *(uint32_t*)&t0; }
            { __nv_bfloat162 t1 = __floats2bfloat162_rn(g0.z, g0.w); pk.y = *(uint32_t*)&t1; }
            { __nv_bfloat162 t2 = __floats2bfloat162_rn(g1.x, g1.y); pk.z = *(uint32_t*)&t2; }
            { __nv_bfloat162 t3 = __floats2bfloat162_rn(g1.z, g1.w); pk.w = *(uint32_t*)&t3; }
            Ys[chunk_off(row, c)] = pk;
        }
        __syncthreads();

#pragma unroll
        for (int ks = 0; ks < 4; ks++) {      // k16 steps within block
            const int sub = lane >> 3;
            const int r   = lane & 7;
            uint32_t A[4][4];
#pragma unroll
            for (int mt = 0; mt < 4; mt++) {
                int rowA = wm * 64 + mt * 16 + (sub & 1) * 8 + r;
                int kch  = ks * 2 + (sub >> 1);
                uint32_t ad = xs_base + (uint32_t)(chunk_off(rowA, kch) << 4);
                ldsm_x4(A[mt][0], A[mt][1], A[mt][2], A[mt][3], ad);
            }
            uint32_t Bf[2][4];
#pragma unroll
            for (int g2 = 0; g2 < 2; g2++) {
                int rowB = wn * 32 + g2 * 16 + (sub >> 1) * 8 + r;
                int kch  = ks * 2 + (sub & 1);
                uint32_t ad = ys_base + (uint32_t)(chunk_off(rowB, kch) << 4);
                ldsm_x4(Bf[g2][0], Bf[g2][1], Bf[g2][2], Bf[g2][3], ad);
            }
#pragma unroll
            for (int mt = 0; mt < 4; mt++)
#pragma unroll
                for (int nt = 0; nt < 4; nt++) {
                    int g2 = nt >> 1, h = nt & 1;
                    mma_bf16(acc[mt][nt][0], acc[mt][nt][1], acc[mt][nt][2], acc[mt][nt][3],
                             A[mt][0], A[mt][1], A[mt][2], A[mt][3],
                             Bf[g2][h * 2 + 0], Bf[g2][h * 2 + 1]);
                }
        }
        __syncthreads();
    }

    __half* cb = g_cost + (size_t)b * KN * KN;
    const int g = lane >> 2, t = lane & 3;
#pragma unroll
    for (int mt = 0; mt < 4; mt++)
#pragma unroll
        for (int nt = 0; nt < 4; nt++) {
            int row0 = wm * 64 + mt * 16 + g;
            int col  = wn * 32 + nt * 8 + 2 * t;
            *(__half2*)(cb + row0 * KN + col) =
                __floats2half2_rn(-acc[mt][nt][0], -acc[mt][nt][1]);
            *(__half2*)(cb + (row0 + 8) * KN + col) =
                __floats2half2_rn(-acc[mt][nt][2], -acc[mt][nt][3]);
        }
}

// ---------------------------------------------------------------------------
// Kernel 2: full Jonker-Volgenant LAP, one warp/batch, fp16 tile (32 KB).
// Phases: column reduction -> augmenting row reduction (2 passes) -> SAP.
// Lane owns 4 consecutive columns; v in registers; warp argmin via one
// redux.sync.min on keys with the column index in the low 7 bits.
// ---------------------------------------------------------------------------
__global__ __launch_bounds__(32) void hungarian_kernel() {
    extern __shared__ __half a_s[];        // 128*128 halfs = 32 KB
    __shared__ int2 pu_s[KN + 1];          // [col 1-based] = {row (1-based,0=free), u_bits}
    __shared__ int  claim_s[KN + 1];       // [row 1-based] = claiming col (0-based)
    __shared__ int  colrow_s[KN];          // [col 0-based] = row (1-based, 0=free)
    __shared__ int  freerows_s[KN];

    const int b = blockIdx.x;
    const int lane = threadIdx.x;
    const float INF = 1e30f;
    const int SENT = 0x7fffffff;

    {   // load cost tile (2048 uint4)
        const uint4* src = (const uint4*)(g_cost + (size_t)b * KN * KN);
        uint4* dst = (uint4*)a_s;
#pragma unroll
        for (int q = 0; q < 64; q++) dst[lane + 32 * q] = src[lane + 32 * q];
    }
    for (int t = lane; t <= KN; t += 32) claim_s[t] = SENT;
    __syncwarp();

    // ---- phase 1: column reduction: v[j] = min_i a[i][j], greedy claim ----
    float v_r[4] = {INF, INF, INF, INF};
    int   argr[4] = {1, 1, 1, 1};
    for (int r = 0; r < KN; r++) {
        uint2 rw = *(const uint2*)(a_s + r * KN + 4 * lane);
        float2 f01 = __half22float2(*(const __half2*)&rw.x);
        float2 f23 = __half22float2(*(const __half2*)&rw.y);
        float av[4] = { f01.x, f01.y, f23.x, f23.y };
#pragma unroll
        for (int c = 0; c < 4; c++)
            if (av[c] < v_r[c]) { v_r[c] = av[c]; argr[c] = r + 1; }
    }
#pragma unroll
    for (int c = 0; c < 4; c++)
        atomicMin(&claim_s[argr[c]], 4 * lane + c);   // lowest col wins row
    __syncwarp();
#pragma unroll
    for (int c = 0; c < 4; c++) {
        int j = 4 * lane + c;
        colrow_s[j] = (claim_s[argr[c]] == j) ? argr[c] : 0;
    }
    __syncwarp();

    // ---- build initial free-row list ----
    int cnt = 0;
#pragma unroll
    for (int g = 0; g < 4; g++) {
        int row = g * 32 + lane + 1;
        bool fr = (claim_s[row] == SENT);
        unsigned m = __ballot_sync(0xffffffffu, fr);
        int pos = __popc(m & ((1u << lane) - 1));
        if (fr) freerows_s[cnt + pos] = row;
        cnt += __popc(m);
    }
    __syncwarp();

    // ---- phase 2: augmenting row reduction (2 passes) ----
    for (int pass = 0; pass < 2; pass++) {
        int prv = cnt;
        int k = 0, nf2 = 0;
        while (k < prv) {
            int irow = freerows_s[k]; k++;
            // two minima of a[irow][j] - v[j]
            uint2 rw = *(const uint2*)(a_s + (irow - 1) * KN + 4 * lane);
            float2 f01 = __half22float2(*(const __half2*)&rw.x);
            float2 f23 = __half22float2(*(const __half2*)&rw.y);
            float h[4] = { f01.x - v_r[0], f01.y - v_r[1],
                           f23.x - v_r[2], f23.y - v_r[3] };
            unsigned kq[4];
            unsigned loc = 0xffffffffu;
#pragma unroll
            for (int c = 0; c < 4; c++) {
                kq[c] = (ordkey(h[c]) & ~127u) | (unsigned)(4 * lane + c);
                loc = min(loc, kq[c]);
            }
            unsigned k1 = redux_min_u32(loc);
            int j1 = k1 & 127;
            unsigned loc2 = 0xffffffffu;
#pragma unroll
            for (int c = 0; c < 4; c++)
                if (4 * lane + c != j1) loc2 = min(loc2, kq[c]);
            unsigned k2 = redux_min_u32(loc2);
            bool strict = (k1 & ~127u) < (k2 & ~127u);

            int i0 = colrow_s[j1];
            if (strict) {
                float u1 = unordkey(k1 & ~127u);
                float u2 = unordkey(k2 & ~127u);
                if ((j1 >> 2) == lane) v_r[j1 & 3] -= (u2 - u1);
            } else if (i0 != 0) {
                j1 = k2 & 127;
                i0 = colrow_s[j1];
            }
            if (lane == 0) colrow_s[j1] = irow;
            if (i0 != 0) {
                if (strict) {
                    k--;
                    if (lane == 0) freerows_s[k] = i0;   // reprocess next
                } else {
                    if (lane == 0) freerows_s[nf2] = i0; // defer to next pass
                    nf2++;
                }
            }
            __syncwarp();
        }
        cnt = nf2;
    }

    // ---- materialize pu (per-column {row, u}) for the SAP phase ----
#pragma unroll
    for (int c = 0; c < 4; c++) {
        int j = 4 * lane + c;
        int row = colrow_s[j];
        float u = 0.f;
        if (row) u = __half2float(a_s[(row - 1) * KN + j]) - v_r[c];
        pu_s[j + 1] = make_int2(row, __float_as_int(u));
    }
    __syncwarp();

    // ---- phase 3: shortest augmenting paths for remaining free rows ----
    for (int t = 0; t < cnt; t++) {
        const int irow = freerows_s[t];
        float dist[4] = {INF, INF, INF, INF};
        int   way[4]  = {0, 0, 0, 0};
        bool  used[4] = {false, false, false, false};
        int   i0 = irow;
        float u_i0 = 0.f;
        float D  = 0.f;
        int   prevj = 0;
        int   j0;

        for (;;) {
            const float s = D - u_i0;
            uint2 rw = *(const uint2*)(a_s + (i0 - 1) * KN + 4 * lane);
            float2 f01 = __half22float2(*(const __half2*)&rw.x);
            float2 f23 = __half22float2(*(const __half2*)&rw.y);
            float av[4] = { f01.x, f01.y, f23.x, f23.y };

            unsigned bestkey = 0xffffffffu;
#pragma unroll
            for (int c = 0; c < 4; c++) {
                if (!used[c]) {
                    float cur = av[c] + (s - v_r[c]);
                    if (cur < dist[c]) { dist[c] = cur; way[c] = prevj; }
                    unsigned k = (ordkey(dist[c]) & ~127u) | (unsigned)(4 * lane + c);
                    bestkey = min(bestkey, k);
                }
            }
            unsigned mk = redux_min_u32(bestkey);
            D = unordkey(mk);                 // uniform across lanes
            int jg = mk & 127;                // winning column, 0-based
            int j1 = jg + 1;
            prevj = j1;

            int2 pu = pu_s[j1];               // {row, u}, one LDS.64
            bool done = (pu.x == 0);
            if (!done && (jg >> 2) == lane) used[jg & 3] = true;
            if (done) { j0 = j1; break; }
            i0 = pu.x;
            u_i0 = __int_as_float(pu.y);
        }

        // deferred dual updates (old matching; each matched row in exactly 1 col)
#pragma unroll
        for (int c = 0; c < 4; c++) {
            if (used[c]) {
                float dd = D - dist[c];
                v_r[c] -= dd;
                int j = 4 * lane + c + 1;
                pu_s[j].y = __float_as_int(__int_as_float(pu_s[j].y) + dd);
            }
        }
        if (lane == 0) pu_s[0] = make_int2(irow, __float_as_int(D));
        __syncwarp();

        // augment: shift {row,u} pairs along alternating path
        int jj = j0;
        while (jj != 0) {
            int o = jj - 1;
            int c = o & 3;
            int sel = (c == 0) ? way[0] : (c == 1) ? way[1] : (c == 2) ? way[2] : way[3];
            int jn = __shfl_sync(0xffffffffu, sel, o >> 2);
            if (lane == 0) pu_s[jj] = pu_s[jn];
            __syncwarp();
            jj = jn;
        }
        __syncwarp();
    }

    // emit row->col permutation: perm[row-1] = col-1
#pragma unroll
    for (int c = 0; c < 4; c++) {
        int j = 4 * lane + c + 1;
        g_perm[b * KN + pu_s[j].x - 1] = j - 1;
    }
}

// ---------------------------------------------------------------------------
// Kernel 3: per-batch sum of (x - y[perm])^2 in fp32, deterministic reduction
// ---------------------------------------------------------------------------
__global__ __launch_bounds__(256) void mse_kernel(const float* __restrict__ X,
                                                  const float* __restrict__ Y) {
    int b = blockIdx.x, tid = threadIdx.x;
    __shared__ int sperm[KN];
    if (tid < KN) sperm[tid] = g_perm[b * KN + tid];
    __syncthreads();

    const float4* xb = (const float4*)(X + (size_t)b * KN * DN);
    const float4* yb = (const float4*)(Y + (size_t)b * KN * DN);
    const int F4_PER_ROW = DN / 4;   // 128
    float acc = 0.f;
    for (int idx = tid; idx < KN * F4_PER_ROW; idx += 256) {
        int row = idx >> 7, col = idx & (F4_PER_ROW - 1);
        float4 xv = xb[row * F4_PER_ROW + col];
        float4 yv = yb[sperm[row] * F4_PER_ROW + col];
        float d0 = xv.x - yv.x, d1 = xv.y - yv.y;
        float d2 = xv.z - yv.z, d3 = xv.w - yv.w;
        acc += d0 * d0 + d1 * d1 + d2 * d2 + d3 * d3;
    }
    __shared__ double sred[256];
    sred[tid] = (double)acc;
    __syncthreads();
    for (int s = 128; s; s >>= 1) {
        if (tid < s) sred[tid] += sred[tid + s];
        __syncthreads();
    }
    if (tid == 0) g_partial[b] = sred[0];
}

__global__ __launch_bounds__(512) void finalize_kernel(float* __restrict__ out) {
    __shared__ double s[BN];
    int t = threadIdx.x;
    s[t] = g_partial[t];
    __syncthreads();
    for (int st = 256; st; st >>= 1) {
        if (t < st) s[t] += s[t + st];
        __syncthreads();
    }
    if (t == 0) out[0] = (float)(s[0] / ((double)BN * KN * DN));
}

// ---------------------------------------------------------------------------
extern "C" void kernel_launch(void* const* d_in, const int* in_sizes, int n_in,
                              void* d_out, int out_size) {
    const float* X = (const float*)d_in[0];   // input
    const float* Y = (const float*)d_in[1];   // target
    float* out = (float*)d_out;

    cost_kernel<<<BN, 256>>>(X, Y);
    hungarian_kernel<<<BN, 32, KN * KN * (int)sizeof(__half)>>>();
    mse_kernel<<<BN, 256>>>(X, Y);
    finalize_kernel<<<1, 512>>>(out);
}

// round 10
// speedup vs baseline: 1.1165x; 1.1165x over previous
#include <cuda_runtime.h>
#include <cuda_fp16.h>
#include <cuda_bf16.h>
#include <cstdint>

#define BN 512   // batches
#define KN 128   // points per batch
#define DN 512   // feature dim

// Scratch (static device allocations allowed)
__device__ __half  g_cost[(size_t)BN * KN * KN];   // 16.8 MB, cost = -x.y (fp16)
__device__ double  g_partial[BN];                  // per-batch  sum|x|^2 + sum|y|^2
__device__ float   g_dotC[BN];                     // per-batch  sum_i C[i, perm(i)]

// ---------------------------------------------------------------------------
// helpers
// ---------------------------------------------------------------------------
__device__ __forceinline__ uint32_t smem_u32(const void* p) {
    return (uint32_t)__cvta_generic_to_shared(p);
}
__device__ __forceinline__ void ldsm_x4(uint32_t& r0, uint32_t& r1,
                                        uint32_t& r2, uint32_t& r3, uint32_t addr) {
    asm volatile("ldmatrix.sync.aligned.m8n8.x4.shared.b16 {%0,%1,%2,%3}, [%4];"
                 : "=r"(r0), "=r"(r1), "=r"(r2), "=r"(r3) : "r"(addr));
}
__device__ __forceinline__ void mma_bf16(float& c0, float& c1, float& c2, float& c3,
                                         uint32_t a0, uint32_t a1, uint32_t a2, uint32_t a3,
                                         uint32_t b0, uint32_t b1) {
    asm volatile("mma.sync.aligned.m16n8k16.row.col.f32.bf16.bf16.f32 "
                 "{%0,%1,%2,%3}, {%4,%5,%6,%7}, {%8,%9}, {%0,%1,%2,%3};"
                 : "+f"(c0), "+f"(c1), "+f"(c2), "+f"(c3)
                 : "r"(a0), "r"(a1), "r"(a2), "r"(a3), "r"(b0), "r"(b1));
}
__device__ __forceinline__ unsigned redux_min_u32(unsigned v) {
    unsigned r;
    asm("redux.sync.min.u32 %0, %1, 0xffffffff;" : "=r"(r) : "r"(v));
    return r;
}
__device__ __forceinline__ unsigned ordkey(float f) {
    unsigned u = __float_as_uint(f);
    return (u & 0x80000000u) ? ~u : (u | 0x80000000u);
}
__device__ __forceinline__ float unordkey(unsigned k) {
    unsigned u = (k & 0x80000000u) ? (k & 0x7fffffffu) : ~k;
    return __uint_as_float(u);
}

// ---------------------------------------------------------------------------
// Kernel 1: C[b][i][j] = -(X[b,i,:] . Y[b,j,:]), bf16 MMA, fp16 output.
// Also accumulates per-batch sum|x|^2 + sum|y|^2 (each element loaded once).
// One CTA per batch. 256 thr = 8 warps in a 2(M) x 4(N) grid; warp tile 64x32.
// ---------------------------------------------------------------------------
__device__ __forceinline__ int chunk_off(int row, int c) {   // in 16B units
    return row * 8 + (c ^ (row & 7));
}

__global__ __launch_bounds__(256) void cost_kernel(const float* __restrict__ X,
                                                   const float* __restrict__ Y) {
    __shared__ uint4 Xs[1024];   // 16 KB: 128 rows x 8 chunks
    __shared__ uint4 Ys[1024];   // 16 KB
    __shared__ double nred[256];

    const int b   = blockIdx.x;
    const int tid = threadIdx.x;
    const int w    = tid >> 5;
    const int lane = tid & 31;
    const int wm = w >> 2;       // 0..1  -> m base = wm*64
    const int wn = w & 3;        // 0..3  -> n base = wn*32

    const float* xb = X + (size_t)b * KN * DN;
    const float* yb = Y + (size_t)b * KN * DN;

    float acc[4][4][4];
#pragma unroll
    for (int mt = 0; mt < 4; mt++)
#pragma unroll
        for (int nt = 0; nt < 4; nt++)
#pragma unroll
            for (int q = 0; q < 4; q++) acc[mt][nt][q] = 0.f;

    float nacc = 0.f;   // per-thread sum of squares (X and Y elements it loads)

    const uint32_t xs_base = smem_u32(Xs);
    const uint32_t ys_base = smem_u32(Ys);

    for (int kb = 0; kb < 8; kb++) {     // K blocks of 64
#pragma unroll
        for (int qi = 0; qi < 4; qi++) {
            int q   = tid + 256 * qi;    // 0..1023
            int row = q >> 3;
            int c   = q & 7;
            const float* sx = xb + row * DN + kb * 64 + c * 8;
            const float* sy = yb + row * DN + kb * 64 + c * 8;
            float4 f0 = *(const float4*)sx;
            float4 f1 = *(const float4*)(sx + 4);
            nacc += f0.x * f0.x + f0.y * f0.y + f0.z * f0.z + f0.w * f0.w
                  + f1.x * f1.x + f1.y * f1.y + f1.z * f1.z + f1.w * f1.w;
            uint4 pk;
            { __nv_bfloat162 t0 = __floats2bfloat162_rn(f0.x, f0.y); pk.x = *(uint32_t*)&t0; }
            { __nv_bfloat162 t1 = __floats2bfloat162_rn(f0.z, f0.w); pk.y = *(uint32_t*)&t1; }
            { __nv_bfloat162 t2 = __floats2bfloat162_rn(f1.x, f1.y); pk.z = *(uint32_t*)&t2; }
            { __nv_bfloat162 t3 = __floats2bfloat162_rn(f1.z, f1.w); pk.w = *(uint32_t*)&t3; }
            Xs[chunk_off(row, c)] = pk;
            float4 g0 = *(const float4*)sy;
            float4 g1 = *(const float4*)(sy + 4);
            nacc += g0.x * g0.x + g0.y * g0.y + g0.z * g0.z + g0.w * g0.w
                  + g1.x * g1.x + g1.y * g1.y + g1.z * g1.z + g1.w * g1.w;
            { __nv_bfloat162 t0 = __floats2bfloat162_rn(g0.x, g0.y); pk.x = *(uint32_t*)&t0; }
            { __nv_bfloat162 t1 = __floats2bfloat162_rn(g0.z, g0.w); pk.y = *(uint32_t*)&t1; }
            { __nv_bfloat162 t2 = __floats2bfloat162_rn(g1.x, g1.y); pk.z = *(uint32_t*)&t2; }
            { __nv_bfloat162 t3 = __floats2bfloat162_rn(g1.z, g1.w); pk.w = *(uint32_t*)&t3; }
            Ys[chunk_off(row, c)] = pk;
        }
        __syncthreads();

#pragma unroll
        for (int ks = 0; ks < 4; ks++) {      // k16 steps within block
            const int sub = lane >> 3;
            const int r   = lane & 7;
            uint32_t A[4][4];
#pragma unroll
            for (int mt = 0; mt < 4; mt++) {
                int rowA = wm * 64 + mt * 16 + (sub & 1) * 8 + r;
                int kch  = ks * 2 + (sub >> 1);
                uint32_t ad = xs_base + (uint32_t)(chunk_off(rowA, kch) << 4);
                ldsm_x4(A[mt][0], A[mt][1], A[mt][2], A[mt][3], ad);
            }
            uint32_t Bf[2][4];
#pragma unroll
            for (int g2 = 0; g2 < 2; g2++) {
                int rowB = wn * 32 + g2 * 16 + (sub >> 1) * 8 + r;
                int kch  = ks * 2 + (sub & 1);
                uint32_t ad = ys_base + (uint32_t)(chunk_off(rowB, kch) << 4);
                ldsm_x4(Bf[g2][0], Bf[g2][1], Bf[g2][2], Bf[g2][3], ad);
            }
#pragma unroll
            for (int mt = 0; mt < 4; mt++)
#pragma unroll
                for (int nt = 0; nt < 4; nt++) {
                    int g2 = nt >> 1, h = nt & 1;
                    mma_bf16(acc[mt][nt][0], acc[mt][nt][1], acc[mt][nt][2], acc[mt][nt][3],
                             A[mt][0], A[mt][1], A[mt][2], A[mt][3],
                             Bf[g2][h * 2 + 0], Bf[g2][h * 2 + 1]);
                }
        }
        __syncthreads();
    }

    // epilogue: negate, write fp16
    __half* cb = g_cost + (size_t)b * KN * KN;
    const int g = lane >> 2, t = lane & 3;
#pragma unroll
    for (int mt = 0; mt < 4; mt++)
#pragma unroll
        for (int nt = 0; nt < 4; nt++) {
            int row0 = wm * 64 + mt * 16 + g;
            int col  = wn * 32 + nt * 8 + 2 * t;
            *(__half2*)(cb + row0 * KN + col) =
                __floats2half2_rn(-acc[mt][nt][0], -acc[mt][nt][1]);
            *(__half2*)(cb + (row0 + 8) * KN + col) =
                __floats2half2_rn(-acc[mt][nt][2], -acc[mt][nt][3]);
        }

    // per-batch norm reduction (deterministic tree)
    nred[tid] = (double)nacc;
    __syncthreads();
    for (int s = 128; s; s >>= 1) {
        if (tid < s) nred[tid] += nred[tid + s];
        __syncthreads();
    }
    if (tid == 0) g_partial[b] = nred[0];
}

// ---------------------------------------------------------------------------
// Kernel 2: Jonker-Volgenant LAP with column-reduction init, one warp/batch.
// Lane owns 4 consecutive columns. v[j] = col min (dual feasible with u=0);
// each column greedily matched to its argmin row (first col wins via
// atomicMin). Only leftover free rows run the Dijkstra SAP phase.
// Epilogue: emit sum_i C[i, perm(i)] (matched fp16 entries, fp32 sum).
// ---------------------------------------------------------------------------
__global__ __launch_bounds__(32) void hungarian_kernel() {
    extern __shared__ __half a_s[];        // 128*128 halfs = 32 KB
    __shared__ int2 pu_s[KN + 1];          // [col] = {row (1-based, 0=free), u_bits}
    __shared__ int  claim_s[KN + 1];       // [row] = claiming column (1-based)
    __shared__ int  freerows_s[KN];

    const int b = blockIdx.x;
    const int lane = threadIdx.x;
    const float INF = 1e30f;
    const int SENT = 0x7fffffff;

    {   // load cost tile (2048 uint4)
        const uint4* src = (const uint4*)(g_cost + (size_t)b * KN * KN);
        uint4* dst = (uint4*)a_s;
#pragma unroll
        for (int q = 0; q < 64; q++) dst[lane + 32 * q] = src[lane + 32 * q];
    }
    for (int t = lane; t <= KN; t += 32) claim_s[t] = SENT;
    __syncwarp();

    // ---- column reduction: v[j] = min_i a[i][j], argmin row per column ----
    float v_r[4] = {INF, INF, INF, INF};
    int   argr[4] = {1, 1, 1, 1};
    for (int r = 0; r < KN; r++) {
        uint2 rw = *(const uint2*)(a_s + r * KN + 4 * lane);
        float2 f01 = __half22float2(*(const __half2*)&rw.x);
        float2 f23 = __half22float2(*(const __half2*)&rw.y);
        float av[4] = { f01.x, f01.y, f23.x, f23.y };
#pragma unroll
        for (int c = 0; c < 4; c++)
            if (av[c] < v_r[c]) { v_r[c] = av[c]; argr[c] = r + 1; }
    }
    // greedy claim: lowest column index wins a contested row
#pragma unroll
    for (int c = 0; c < 4; c++)
        atomicMin(&claim_s[argr[c]], 4 * lane + c + 1);
    __syncwarp();
#pragma unroll
    for (int c = 0; c < 4; c++) {
        int j = 4 * lane + c + 1;
        pu_s[j] = (claim_s[argr[c]] == j) ? make_int2(argr[c], 0)
                                          : make_int2(0, 0);
    }
    __syncwarp();

    // ---- build free-row list (rows not claimed by any column) ----
    int nfree = 0;
#pragma unroll
    for (int g = 0; g < 4; g++) {
        int row = g * 32 + lane + 1;
        bool fr = (claim_s[row] == SENT);
        unsigned m = __ballot_sync(0xffffffffu, fr);
        int pos = __popc(m & ((1u << lane) - 1));
        if (fr) freerows_s[nfree + pos] = row;
        nfree += __popc(m);
    }
    __syncwarp();

    // ---- SAP phase for free rows ----
    for (int t = 0; t < nfree; t++) {
        const int irow = freerows_s[t];
        float dist[4] = {INF, INF, INF, INF};
        int   way[4]  = {0, 0, 0, 0};
        bool  used[4] = {false, false, false, false};
        int   i0 = irow;
        float u_i0 = 0.f;
        float D  = 0.f;
        int   prevj = 0;
        int   j0;

        for (;;) {
            const float s = D - u_i0;
            uint2 rw = *(const uint2*)(a_s + (i0 - 1) * KN + 4 * lane);
            float2 f01 = __half22float2(*(const __half2*)&rw.x);
            float2 f23 = __half22float2(*(const __half2*)&rw.y);
            float av[4] = { f01.x, f01.y, f23.x, f23.y };

            unsigned bestkey = 0xffffffffu;
#pragma unroll
            for (int c = 0; c < 4; c++) {
                if (!used[c]) {
                    float cur = av[c] + (s - v_r[c]);
                    if (cur < dist[c]) { dist[c] = cur; way[c] = prevj; }
                    unsigned k = (ordkey(dist[c]) & ~127u) | (unsigned)(4 * lane + c);
                    bestkey = min(bestkey, k);
                }
            }
            unsigned mk = redux_min_u32(bestkey);
            D = unordkey(mk);                 // uniform across lanes
            int jg = mk & 127;                // winning column, 0-based
            int j1 = jg + 1;
            prevj = j1;

            int2 pu = pu_s[j1];               // {row, u}, one LDS.64
            bool done = (pu.x == 0);
            if (!done && (jg >> 2) == lane) used[jg & 3] = true;
            if (done) { j0 = j1; break; }
            i0 = pu.x;
            u_i0 = __int_as_float(pu.y);
        }

        // deferred dual updates (old matching; each matched row in exactly 1 col)
#pragma unroll
        for (int c = 0; c < 4; c++) {
            if (used[c]) {
                float dd = D - dist[c];
                v_r[c] -= dd;
                int j = 4 * lane + c + 1;
                pu_s[j].y = __float_as_int(__int_as_float(pu_s[j].y) + dd);
            }
        }
        if (lane == 0) pu_s[0] = make_int2(irow, __float_as_int(D));
        __syncwarp();

        // augment: shift {row,u} pairs along alternating path
        int jj = j0;
        while (jj != 0) {
            int o = jj - 1;
            int c = o & 3;
            int sel = (c == 0) ? way[0] : (c == 1) ? way[1] : (c == 2) ? way[2] : way[3];
            int jn = __shfl_sync(0xffffffffu, sel, o >> 2);
            if (lane == 0) pu_s[jj] = pu_s[jn];
            __syncwarp();
            jj = jn;
        }
        __syncwarp();
    }

    // ---- epilogue: sum matched cost entries (C = -x.y) in fp32 ----
    float dsum = 0.f;
#pragma unroll
    for (int c = 0; c < 4; c++) {
        int j = 4 * lane + c + 1;          // this column, 1-based
        int row = pu_s[j].x;               // matched row, 1-based
        dsum += __half2float(a_s[(row - 1) * KN + (j - 1)]);
    }
#pragma unroll
    for (int s = 16; s; s >>= 1)
        dsum += __shfl_xor_sync(0xffffffffu, dsum, s);
    if (lane == 0) g_dotC[b] = dsum;
}

// ---------------------------------------------------------------------------
// Kernel 3: combine  (norms + 2*sum(matched C)) / (B*K*D)
// ---------------------------------------------------------------------------
__global__ __launch_bounds__(512) void finalize_kernel(float* __restrict__ out) {
    __shared__ double s[BN];
    int t = threadIdx.x;
    s[t] = g_partial[t] + 2.0 * (double)g_dotC[t];
    __syncthreads();
    for (int st = 256; st; st >>= 1) {
        if (t < st) s[t] += s[t + st];
        __syncthreads();
    }
    if (t == 0) out[0] = (float)(s[0] / ((double)BN * KN * DN));
}

// ---------------------------------------------------------------------------
extern "C" void kernel_launch(void* const* d_in, const int* in_sizes, int n_in,
                              void* d_out, int out_size) {
    const float* X = (const float*)d_in[0];   // input
    const float* Y = (const float*)d_in[1];   // target
    float* out = (float*)d_out;

    cost_kernel<<<BN, 256>>>(X, Y);
    hungarian_kernel<<<BN, 32, KN * KN * (int)sizeof(__half)>>>();
    finalize_kernel<<<1, 512>>>(out);
}

// round 12
// speedup vs baseline: 1.2211x; 1.0937x over previous
#include <cuda_runtime.h>
#include <cuda_fp16.h>
#include <cuda_bf16.h>
#include <cstdint>

#define BN 512   // batches
#define KN 128   // points per batch
#define DN 512   // feature dim

// Scratch (static device allocations allowed)
__device__ __half  g_cost[(size_t)BN * KN * KN];   // 16.8 MB, cost = -x.y (fp16)
__device__ double  g_norm[2 * BN];                 // per (batch, n-half) norm sums
__device__ float   g_dotC[BN];                     // per-batch  sum_i C[i, perm(i)]

// ---------------------------------------------------------------------------
// helpers
// ---------------------------------------------------------------------------
__device__ __forceinline__ uint32_t smem_u32(const void* p) {
    return (uint32_t)__cvta_generic_to_shared(p);
}
__device__ __forceinline__ void ldsm_x4(uint32_t& r0, uint32_t& r1,
                                        uint32_t& r2, uint32_t& r3, uint32_t addr) {
    asm volatile("ldmatrix.sync.aligned.m8n8.x4.shared.b16 {%0,%1,%2,%3}, [%4];"
                 : "=r"(r0), "=r"(r1), "=r"(r2), "=r"(r3) : "r"(addr));
}
__device__ __forceinline__ void mma_bf16(float& c0, float& c1, float& c2, float& c3,
                                         uint32_t a0, uint32_t a1, uint32_t a2, uint32_t a3,
                                         uint32_t b0, uint32_t b1) {
    asm volatile("mma.sync.aligned.m16n8k16.row.col.f32.bf16.bf16.f32 "
                 "{%0,%1,%2,%3}, {%4,%5,%6,%7}, {%8,%9}, {%0,%1,%2,%3};"
                 : "+f"(c0), "+f"(c1), "+f"(c2), "+f"(c3)
                 : "r"(a0), "r"(a1), "r"(a2), "r"(a3), "r"(b0), "r"(b1));
}
__device__ __forceinline__ unsigned redux_min_u32(unsigned v) {
    unsigned r;
    asm("redux.sync.min.u32 %0, %1, 0xffffffff;" : "=r"(r) : "r"(v));
    return r;
}
__device__ __forceinline__ unsigned ordkey(float f) {
    unsigned u = __float_as_uint(f);
    return (u & 0x80000000u) ? ~u : (u | 0x80000000u);
}
__device__ __forceinline__ float unordkey(unsigned k) {
    unsigned u = (k & 0x80000000u) ? (k & 0x7fffffffu) : ~k;
    return __uint_as_float(u);
}

// ---------------------------------------------------------------------------
// Kernel 1: C[b][i][j] = -(X[b,i,:] . Y[b,j,:]), bf16 MMA, fp16 output.
// Grid = 1024: (batch, n-half). Each CTA computes 128 x 64 of C with 8 warps
// in a 4(M) x 2(N) grid, warp tile 32x32, acc = 32 regs/thread (occupancy!).
// Norms: X counted by nh==0 CTA only; each CTA counts its own Y half.
// ---------------------------------------------------------------------------
__device__ __forceinline__ int chunk_off(int row, int c) {   // in 16B units
    return row * 8 + (c ^ (row & 7));
}

__global__ __launch_bounds__(256) void cost_kernel(const float* __restrict__ X,
                                                   const float* __restrict__ Y) {
    __shared__ uint4 Xs[1024];   // 16 KB: 128 rows x 8 chunks
    __shared__ uint4 Ys[512];    //  8 KB:  64 rows x 8 chunks
    __shared__ double nred[256];

    const int b   = blockIdx.x >> 1;
    const int nh  = blockIdx.x & 1;     // which 64-col half of C / rows of Y
    const int tid = threadIdx.x;
    const int w    = tid >> 5;
    const int lane = tid & 31;
    const int wm = w >> 1;       // 0..3  -> m base = wm*32
    const int wn = w & 1;        // 0..1  -> n base = wn*32

    const float* xb = X + (size_t)b * KN * DN;
    const float* yb = Y + (size_t)b * KN * DN + (size_t)nh * 64 * DN;

    float acc[2][4][4];
#pragma unroll
    for (int mt = 0; mt < 2; mt++)
#pragma unroll
        for (int nt = 0; nt < 4; nt++)
#pragma unroll
            for (int q = 0; q < 4; q++) acc[mt][nt][q] = 0.f;

    float nacc = 0.f;

    const uint32_t xs_base = smem_u32(Xs);
    const uint32_t ys_base = smem_u32(Ys);

    for (int kb = 0; kb < 8; kb++) {     // K blocks of 64
        // X tile: 128 rows x 8 chunks = 1024, 4 per thread
#pragma unroll
        for (int qi = 0; qi < 4; qi++) {
            int q   = tid + 256 * qi;    // 0..1023
            int row = q >> 3;
            int c   = q & 7;
            const float* sx = xb + row * DN + kb * 64 + c * 8;
            float4 f0 = *(const float4*)sx;
            float4 f1 = *(const float4*)(sx + 4);
            if (nh == 0)
                nacc += f0.x * f0.x + f0.y * f0.y + f0.z * f0.z + f0.w * f0.w
                      + f1.x * f1.x + f1.y * f1.y + f1.z * f1.z + f1.w * f1.w;
            uint4 pk;
            { __nv_bfloat162 t0 = __floats2bfloat162_rn(f0.x, f0.y); pk.x = *(uint32_t*)&t0; }
            { __nv_bfloat162 t1 = __floats2bfloat162_rn(f0.z, f0.w); pk.y = *(uint32_t*)&t1; }
            { __nv_bfloat162 t2 = __floats2bfloat162_rn(f1.x, f1.y); pk.z = *(uint32_t*)&t2; }
            { __nv_bfloat162 t3 = __floats2bfloat162_rn(f1.z, f1.w); pk.w = *(uint32_t*)&t3; }
            Xs[chunk_off(row, c)] = pk;
        }
        // Y tile: 64 rows x 8 chunks = 512, 2 per thread
#pragma unroll
        for (int qi = 0; qi < 2; qi++) {
            int q   = tid + 256 * qi;    // 0..511
            int row = q >> 3;            // 0..63
            int c   = q & 7;
            const float* sy = yb + row * DN + kb * 64 + c * 8;
            float4 g0 = *(const float4*)sy;
            float4 g1 = *(const float4*)(sy + 4);
            nacc += g0.x * g0.x + g0.y * g0.y + g0.z * g0.z + g0.w * g0.w
                  + g1.x * g1.x + g1.y * g1.y + g1.z * g1.z + g1.w * g1.w;
            uint4 pk;
            { __nv_bfloat162 t0 = __floats2bfloat162_rn(g0.x, g0.y); pk.x = *(uint32_t*)&t0; }
            { __nv_bfloat162 t1 = __floats2bfloat162_rn(g0.z, g0.w); pk.y = *(uint32_t*)&t1; }
            { __nv_bfloat162 t2 = __floats2bfloat162_rn(g1.x, g1.y); pk.z = *(uint32_t*)&t2; }
            { __nv_bfloat162 t3 = __floats2bfloat162_rn(g1.z, g1.w); pk.w = *(uint32_t*)&t3; }
            Ys[chunk_off(row, c)] = pk;
        }
        __syncthreads();

#pragma unroll
        for (int ks = 0; ks < 4; ks++) {      // k16 steps within block
            const int sub = lane >> 3;
            const int r   = lane & 7;
            uint32_t A[2][4];
#pragma unroll
            for (int mt = 0; mt < 2; mt++) {
                int rowA = wm * 32 + mt * 16 + (sub & 1) * 8 + r;
                int kch  = ks * 2 + (sub >> 1);
                uint32_t ad = xs_base + (uint32_t)(chunk_off(rowA, kch) << 4);
                ldsm_x4(A[mt][0], A[mt][1], A[mt][2], A[mt][3], ad);
            }
            uint32_t Bf[2][4];
#pragma unroll
            for (int g2 = 0; g2 < 2; g2++) {
                int rowB = wn * 32 + g2 * 16 + (sub >> 1) * 8 + r;
                int kch  = ks * 2 + (sub & 1);
                uint32_t ad = ys_base + (uint32_t)(chunk_off(rowB, kch) << 4);
                ldsm_x4(Bf[g2][0], Bf[g2][1], Bf[g2][2], Bf[g2][3], ad);
            }
#pragma unroll
            for (int mt = 0; mt < 2; mt++)
#pragma unroll
                for (int nt = 0; nt < 4; nt++) {
                    int g2 = nt >> 1, h = nt & 1;
                    mma_bf16(acc[mt][nt][0], acc[mt][nt][1], acc[mt][nt][2], acc[mt][nt][3],
                             A[mt][0], A[mt][1], A[mt][2], A[mt][3],
                             Bf[g2][h * 2 + 0], Bf[g2][h * 2 + 1]);
                }
        }
        __syncthreads();
    }

    // epilogue: negate, write fp16
    __half* cb = g_cost + (size_t)b * KN * KN;
    const int g = lane >> 2, t = lane & 3;
#pragma unroll
    for (int mt = 0; mt < 2; mt++)
#pragma unroll
        for (int nt = 0; nt < 4; nt++) {
            int row0 = wm * 32 + mt * 16 + g;
            int col  = nh * 64 + wn * 32 + nt * 8 + 2 * t;
            *(__half2*)(cb + row0 * KN + col) =
                __floats2half2_rn(-acc[mt][nt][0], -acc[mt][nt][1]);
            *(__half2*)(cb + (row0 + 8) * KN + col) =
                __floats2half2_rn(-acc[mt][nt][2], -acc[mt][nt][3]);
        }

    // norm reduction (deterministic tree) for this (batch, half)
    nred[tid] = (double)nacc;
    __syncthreads();
    for (int s = 128; s; s >>= 1) {
        if (tid < s) nred[tid] += nred[tid + s];
        __syncthreads();
    }
    if (tid == 0) g_norm[blockIdx.x] = nred[0];
}

// ---------------------------------------------------------------------------
// Kernel 2: Jonker-Volgenant LAP with column-reduction init, one warp/batch.
// Lane owns 4 consecutive columns. v[j] = col min (dual feasible with u=0);
// each column greedily matched to its argmin row (first col wins via
// atomicMin). Only leftover free rows run the Dijkstra SAP phase.
// Epilogue: emit sum_i C[i, perm(i)] (matched fp16 entries, fp32 sum).
// ---------------------------------------------------------------------------
__global__ __launch_bounds__(32) void hungarian_kernel() {
    extern __shared__ __half a_s[];        // 128*128 halfs = 32 KB
    __shared__ int2 pu_s[KN + 1];          // [col] = {row (1-based, 0=free), u_bits}
    __shared__ int  claim_s[KN + 1];       // [row] = claiming column (1-based)
    __shared__ int  freerows_s[KN];

    const int b = blockIdx.x;
    const int lane = threadIdx.x;
    const float INF = 1e30f;
    const int SENT = 0x7fffffff;

    {   // load cost tile (2048 uint4)
        const uint4* src = (const uint4*)(g_cost + (size_t)b * KN * KN);
        uint4* dst = (uint4*)a_s;
#pragma unroll
        for (int q = 0; q < 64; q++) dst[lane + 32 * q] = src[lane + 32 * q];
    }
    for (int t = lane; t <= KN; t += 32) claim_s[t] = SENT;
    __syncwarp();

    // ---- column reduction: v[j] = min_i a[i][j], argmin row per column ----
    float v_r[4] = {INF, INF, INF, INF};
    int   argr[4] = {1, 1, 1, 1};
    for (int r = 0; r < KN; r++) {
        uint2 rw = *(const uint2*)(a_s + r * KN + 4 * lane);
        float2 f01 = __half22float2(*(const __half2*)&rw.x);
        float2 f23 = __half22float2(*(const __half2*)&rw.y);
        float av[4] = { f01.x, f01.y, f23.x, f23.y };
#pragma unroll
        for (int c = 0; c < 4; c++)
            if (av[c] < v_r[c]) { v_r[c] = av[c]; argr[c] = r + 1; }
    }
    // greedy claim: lowest column index wins a contested row
#pragma unroll
    for (int c = 0; c < 4; c++)
        atomicMin(&claim_s[argr[c]], 4 * lane + c + 1);
    __syncwarp();
#pragma unroll
    for (int c = 0; c < 4; c++) {
        int j = 4 * lane + c + 1;
        pu_s[j] = (claim_s[argr[c]] == j) ? make_int2(argr[c], 0)
                                          : make_int2(0, 0);
    }
    __syncwarp();

    // ---- build free-row list (rows not claimed by any column) ----
    int nfree = 0;
#pragma unroll
    for (int g = 0; g < 4; g++) {
        int row = g * 32 + lane + 1;
        bool fr = (claim_s[row] == SENT);
        unsigned m = __ballot_sync(0xffffffffu, fr);
        int pos = __popc(m & ((1u << lane) - 1));
        if (fr) freerows_s[nfree + pos] = row;
        nfree += __popc(m);
    }
    __syncwarp();

    // ---- SAP phase for free rows ----
    for (int t = 0; t < nfree; t++) {
        const int irow = freerows_s[t];
        float dist[4] = {INF, INF, INF, INF};
        int   way[4]  = {0, 0, 0, 0};
        bool  used[4] = {false, false, false, false};
        int   i0 = irow;
        float u_i0 = 0.f;
        float D  = 0.f;
        int   prevj = 0;
        int   j0;

        for (;;) {
            const float s = D - u_i0;
            uint2 rw = *(const uint2*)(a_s + (i0 - 1) * KN + 4 * lane);
            float2 f01 = __half22float2(*(const __half2*)&rw.x);
            float2 f23 = __half22float2(*(const __half2*)&rw.y);
            float av[4] = { f01.x, f01.y, f23.x, f23.y };

            unsigned bestkey = 0xffffffffu;
#pragma unroll
            for (int c = 0; c < 4; c++) {
                if (!used[c]) {
                    float cur = av[c] + (s - v_r[c]);
                    if (cur < dist[c]) { dist[c] = cur; way[c] = prevj; }
                    unsigned k = (ordkey(dist[c]) & ~127u) | (unsigned)(4 * lane + c);
                    bestkey = min(bestkey, k);
                }
            }
            unsigned mk = redux_min_u32(bestkey);
            D = unordkey(mk);                 // uniform across lanes
            int jg = mk & 127;                // winning column, 0-based
            int j1 = jg + 1;
            prevj = j1;

            int2 pu = pu_s[j1];               // {row, u}, one LDS.64
            bool done = (pu.x == 0);
            if (!done && (jg >> 2) == lane) used[jg & 3] = true;
            if (done) { j0 = j1; break; }
            i0 = pu.x;
            u_i0 = __int_as_float(pu.y);
        }

        // deferred dual updates (old matching; each matched row in exactly 1 col)
#pragma unroll
        for (int c = 0; c < 4; c++) {
            if (used[c]) {
                float dd = D - dist[c];
                v_r[c] -= dd;
                int j = 4 * lane + c + 1;
                pu_s[j].y = __float_as_int(__int_as_float(pu_s[j].y) + dd);
            }
        }
        if (lane == 0) pu_s[0] = make_int2(irow, __float_as_int(D));
        __syncwarp();

        // augment: shift {row,u} pairs along alternating path
        int jj = j0;
        while (jj != 0) {
            int o = jj - 1;
            int c = o & 3;
            int sel = (c == 0) ? way[0] : (c == 1) ? way[1] : (c == 2) ? way[2] : way[3];
            int jn = __shfl_sync(0xffffffffu, sel, o >> 2);
            if (lane == 0) pu_s[jj] = pu_s[jn];
            __syncwarp();
            jj = jn;
        }
        __syncwarp();
    }

    // ---- epilogue: sum matched cost entries (C = -x.y) in fp32 ----
    float dsum = 0.f;
#pragma unroll
    for (int c = 0; c < 4; c++) {
        int j = 4 * lane + c + 1;          // this column, 1-based
        int row = pu_s[j].x;               // matched row, 1-based
        dsum += __half2float(a_s[(row - 1) * KN + (j - 1)]);
    }
#pragma unroll
    for (int s = 16; s; s >>= 1)
        dsum += __shfl_xor_sync(0xffffffffu, dsum, s);
    if (lane == 0) g_dotC[b] = dsum;
}

// ---------------------------------------------------------------------------
// Kernel 3: combine  (norms + 2*sum(matched C)) / (B*K*D)
// ---------------------------------------------------------------------------
__global__ __launch_bounds__(512) void finalize_kernel(float* __restrict__ out) {
    __shared__ double s[BN];
    int t = threadIdx.x;
    s[t] = g_norm[2 * t] + g_norm[2 * t + 1] + 2.0 * (double)g_dotC[t];
    __syncthreads();
    for (int st = 256; st; st >>= 1) {
        if (t < st) s[t] += s[t + st];
        __syncthreads();
    }
    if (t == 0) out[0] = (float)(s[0] / ((double)BN * KN * DN));
}

// ---------------------------------------------------------------------------
extern "C" void kernel_launch(void* const* d_in, const int* in_sizes, int n_in,
                              void* d_out, int out_size) {
    const float* X = (const float*)d_in[0];   // input
    const float* Y = (const float*)d_in[1];   // target
    float* out = (float*)d_out;

    cost_kernel<<<2 * BN, 256>>>(X, Y);
    hungarian_kernel<<<BN, 32, KN * KN * (int)sizeof(__half)>>>();
    finalize_kernel<<<1, 512>>>(out);
}

// round 13
// speedup vs baseline: 1.8068x; 1.4796x over previous
#include <cuda_runtime.h>
#include <cuda_fp16.h>
#include <cuda_bf16.h>
#include <cstdint>

#define BN 512   // batches
#define KN 128   // points per batch
#define DN 512   // feature dim

// Scratch (static device allocations allowed)
__device__ __half  g_cost[(size_t)BN * KN * KN];   // 16.8 MB, cost = -x.y (fp16)
__device__ double  g_norm[2 * BN];                 // per (batch, n-half) norm sums
__device__ float   g_dotC[BN];                     // per-batch  sum_i C[i, perm(i)]

// ---------------------------------------------------------------------------
// helpers
// ---------------------------------------------------------------------------
__device__ __forceinline__ uint32_t smem_u32(const void* p) {
    return (uint32_t)__cvta_generic_to_shared(p);
}
__device__ __forceinline__ void ldsm_x4(uint32_t& r0, uint32_t& r1,
                                        uint32_t& r2, uint32_t& r3, uint32_t addr) {
    asm volatile("ldmatrix.sync.aligned.m8n8.x4.shared.b16 {%0,%1,%2,%3}, [%4];"
                 : "=r"(r0), "=r"(r1), "=r"(r2), "=r"(r3) : "r"(addr));
}
__device__ __forceinline__ void mma_bf16(float& c0, float& c1, float& c2, float& c3,
                                         uint32_t a0, uint32_t a1, uint32_t a2, uint32_t a3,
                                         uint32_t b0, uint32_t b1) {
    asm volatile("mma.sync.aligned.m16n8k16.row.col.f32.bf16.bf16.f32 "
                 "{%0,%1,%2,%3}, {%4,%5,%6,%7}, {%8,%9}, {%0,%1,%2,%3};"
                 : "+f"(c0), "+f"(c1), "+f"(c2), "+f"(c3)
                 : "r"(a0), "r"(a1), "r"(a2), "r"(a3), "r"(b0), "r"(b1));
}
__device__ __forceinline__ unsigned redux_min_u32(unsigned v) {
    unsigned r;
    asm("redux.sync.min.u32 %0, %1, 0xffffffff;" : "=r"(r) : "r"(v));
    return r;
}
__device__ __forceinline__ unsigned ordkey(float f) {
    unsigned u = __float_as_uint(f);
    return (u & 0x80000000u) ? ~u : (u | 0x80000000u);
}
__device__ __forceinline__ float unordkey(unsigned k) {
    unsigned u = (k & 0x80000000u) ? (k & 0x7fffffffu) : ~k;
    return __uint_as_float(u);
}

// ---------------------------------------------------------------------------
// Kernel 1: C[b][i][j] = -(X[b,i,:] . Y[b,j,:]), bf16 MMA, fp16 output.
// Grid = 1024: (batch, n-half). Each CTA computes 128 x 64 of C with 8 warps
// in a 4(M) x 2(N) grid, warp tile 32x32, acc = 32 regs/thread.
// Norms: X counted by nh==0 CTA only; each CTA counts its own Y half.
// ---------------------------------------------------------------------------
__device__ __forceinline__ int chunk_off(int row, int c) {   // in 16B units
    return row * 8 + (c ^ (row & 7));
}

__global__ __launch_bounds__(256) void cost_kernel(const float* __restrict__ X,
                                                   const float* __restrict__ Y) {
    __shared__ uint4 Xs[1024];   // 16 KB: 128 rows x 8 chunks
    __shared__ uint4 Ys[512];    //  8 KB:  64 rows x 8 chunks
    __shared__ double nred[256];

    const int b   = blockIdx.x >> 1;
    const int nh  = blockIdx.x & 1;     // which 64-col half of C / rows of Y
    const int tid = threadIdx.x;
    const int w    = tid >> 5;
    const int lane = tid & 31;
    const int wm = w >> 1;       // 0..3  -> m base = wm*32
    const int wn = w & 1;        // 0..1  -> n base = wn*32

    const float* xb = X + (size_t)b * KN * DN;
    const float* yb = Y + (size_t)b * KN * DN + (size_t)nh * 64 * DN;

    float acc[2][4][4];
#pragma unroll
    for (int mt = 0; mt < 2; mt++)
#pragma unroll
        for (int nt = 0; nt < 4; nt++)
#pragma unroll
            for (int q = 0; q < 4; q++) acc[mt][nt][q] = 0.f;

    float nacc = 0.f;

    const uint32_t xs_base = smem_u32(Xs);
    const uint32_t ys_base = smem_u32(Ys);

    for (int kb = 0; kb < 8; kb++) {     // K blocks of 64
#pragma unroll
        for (int qi = 0; qi < 4; qi++) {
            int q   = tid + 256 * qi;    // 0..1023
            int row = q >> 3;
            int c   = q & 7;
            const float* sx = xb + row * DN + kb * 64 + c * 8;
            float4 f0 = *(const float4*)sx;
            float4 f1 = *(const float4*)(sx + 4);
            if (nh == 0)
                nacc += f0.x * f0.x + f0.y * f0.y + f0.z * f0.z + f0.w * f0.w
                      + f1.x * f1.x + f1.y * f1.y + f1.z * f1.z + f1.w * f1.w;
            uint4 pk;
            { __nv_bfloat162 t0 = __floats2bfloat162_rn(f0.x, f0.y); pk.x = *(uint32_t*)&t0; }
            { __nv_bfloat162 t1 = __floats2bfloat162_rn(f0.z, f0.w); pk.y = *(uint32_t*)&t1; }
            { __nv_bfloat162 t2 = __floats2bfloat162_rn(f1.x, f1.y); pk.z = *(uint32_t*)&t2; }
            { __nv_bfloat162 t3 = __floats2bfloat162_rn(f1.z, f1.w); pk.w = *(uint32_t*)&t3; }
            Xs[chunk_off(row, c)] = pk;
        }
#pragma unroll
        for (int qi = 0; qi < 2; qi++) {
            int q   = tid + 256 * qi;    // 0..511
            int row = q >> 3;            // 0..63
            int c   = q & 7;
            const float* sy = yb + row * DN + kb * 64 + c * 8;
            float4 g0 = *(const float4*)sy;
            float4 g1 = *(const float4*)(sy + 4);
            nacc += g0.x * g0.x + g0.y * g0.y + g0.z * g0.z + g0.w * g0.w
                  + g1.x * g1.x + g1.y * g1.y + g1.z * g1.z + g1.w * g1.w;
            uint4 pk;
            { __nv_bfloat162 t0 = __floats2bfloat162_rn(g0.x, g0.y); pk.x = *(uint32_t*)&t0; }
            { __nv_bfloat162 t1 = __floats2bfloat162_rn(g0.z, g0.w); pk.y = *(uint32_t*)&t1; }
            { __nv_bfloat162 t2 = __floats2bfloat162_rn(g1.x, g1.y); pk.z = *(uint32_t*)&t2; }
            { __nv_bfloat162 t3 = __floats2bfloat162_rn(g1.z, g1.w); pk.w = *(uint32_t*)&t3; }
            Ys[chunk_off(row, c)] = pk;
        }
        __syncthreads();

#pragma unroll
        for (int ks = 0; ks < 4; ks++) {      // k16 steps within block
            const int sub = lane >> 3;
            const int r   = lane & 7;
            uint32_t A[2][4];
#pragma unroll
            for (int mt = 0; mt < 2; mt++) {
                int rowA = wm * 32 + mt * 16 + (sub & 1) * 8 + r;
                int kch  = ks * 2 + (sub >> 1);
                uint32_t ad = xs_base + (uint32_t)(chunk_off(rowA, kch) << 4);
                ldsm_x4(A[mt][0], A[mt][1], A[mt][2], A[mt][3], ad);
            }
            uint32_t Bf[2][4];
#pragma unroll
            for (int g2 = 0; g2 < 2; g2++) {
                int rowB = wn * 32 + g2 * 16 + (sub >> 1) * 8 + r;
                int kch  = ks * 2 + (sub & 1);
                uint32_t ad = ys_base + (uint32_t)(chunk_off(rowB, kch) << 4);
                ldsm_x4(Bf[g2][0], Bf[g2][1], Bf[g2][2], Bf[g2][3], ad);
            }
#pragma unroll
            for (int mt = 0; mt < 2; mt++)
#pragma unroll
                for (int nt = 0; nt < 4; nt++) {
                    int g2 = nt >> 1, h = nt & 1;
                    mma_bf16(acc[mt][nt][0], acc[mt][nt][1], acc[mt][nt][2], acc[mt][nt][3],
                             A[mt][0], A[mt][1], A[mt][2], A[mt][3],
                             Bf[g2][h * 2 + 0], Bf[g2][h * 2 + 1]);
                }
        }
        __syncthreads();
    }

    __half* cb = g_cost + (size_t)b * KN * KN;
    const int g = lane >> 2, t = lane & 3;
#pragma unroll
    for (int mt = 0; mt < 2; mt++)
#pragma unroll
        for (int nt = 0; nt < 4; nt++) {
            int row0 = wm * 32 + mt * 16 + g;
            int col  = nh * 64 + wn * 32 + nt * 8 + 2 * t;
            *(__half2*)(cb + row0 * KN + col) =
                __floats2half2_rn(-acc[mt][nt][0], -acc[mt][nt][1]);
            *(__half2*)(cb + (row0 + 8) * KN + col) =
                __floats2half2_rn(-acc[mt][nt][2], -acc[mt][nt][3]);
        }

    nred[tid] = (double)nacc;
    __syncthreads();
    for (int s = 128; s; s >>= 1) {
        if (tid < s) nred[tid] += nred[tid + s];
        __syncthreads();
    }
    if (tid == 0) g_norm[blockIdx.x] = nred[0];
}

// ---------------------------------------------------------------------------
// Kernel 2: Jonker-Volgenant LAP, one warp/batch, fp16 tile (32 KB).
// Full JV init: ROW reduction (u[i] = row min) then COLUMN reduction
// (v[j] = min_i (a - u)), greedy claim on zero reduced costs, then Dijkstra
// SAP for leftover free rows (supports arbitrary u).
// Epilogue: emit sum_i C[i, perm(i)] (matched fp16 entries, fp32 sum).
// ---------------------------------------------------------------------------
__global__ __launch_bounds__(32) void hungarian_kernel() {
    extern __shared__ __half a_s[];        // 128*128 halfs = 32 KB
    __shared__ int2  pu_s[KN + 1];         // [col] = {row (1-based, 0=free), u_bits}
    __shared__ int   claim_s[KN + 1];      // [row] = claiming column (1-based)
    __shared__ int   freerows_s[KN];
    __shared__ float urow_s[KN + 1];       // [row 1-based] = row reduction u[i]

    const int b = blockIdx.x;
    const int lane = threadIdx.x;
    const float INF = 1e30f;
    const int SENT = 0x7fffffff;

    {   // load cost tile (2048 uint4)
        const uint4* src = (const uint4*)(g_cost + (size_t)b * KN * KN);
        uint4* dst = (uint4*)a_s;
#pragma unroll
        for (int q = 0; q < 64; q++) dst[lane + 32 * q] = src[lane + 32 * q];
    }
    for (int t = lane; t <= KN; t += 32) claim_s[t] = SENT;
    __syncwarp();

    // ---- phase 0: row reduction  u[i] = min_j a[i][j] ----
    for (int r = 0; r < KN; r++) {
        uint2 rw = *(const uint2*)(a_s + r * KN + 4 * lane);
        __half2 h01 = *(const __half2*)&rw.x;
        __half2 h23 = *(const __half2*)&rw.y;
        __half2 m2 = __hmin2(h01, h23);
        float m = fminf(__low2float(m2), __high2float(m2));
        unsigned mk = redux_min_u32(ordkey(m));
        if (lane == 0) urow_s[r + 1] = unordkey(mk);
    }
    __syncwarp();

    // ---- phase 1: column reduction on reduced costs ----
    // v[j] = min_i (a[i][j] - u[i]), remember argmin row per column
    float v_r[4] = {INF, INF, INF, INF};
    int   argr[4] = {1, 1, 1, 1};
    for (int r = 0; r < KN; r++) {
        float ur = urow_s[r + 1];
        uint2 rw = *(const uint2*)(a_s + r * KN + 4 * lane);
        float2 f01 = __half22float2(*(const __half2*)&rw.x);
        float2 f23 = __half22float2(*(const __half2*)&rw.y);
        float av[4] = { f01.x - ur, f01.y - ur, f23.x - ur, f23.y - ur };
#pragma unroll
        for (int c = 0; c < 4; c++)
            if (av[c] < v_r[c]) { v_r[c] = av[c]; argr[c] = r + 1; }
    }
    // greedy claim: lowest column index wins a contested row
#pragma unroll
    for (int c = 0; c < 4; c++)
        atomicMin(&claim_s[argr[c]], 4 * lane + c + 1);
    __syncwarp();
#pragma unroll
    for (int c = 0; c < 4; c++) {
        int j = 4 * lane + c + 1;
        pu_s[j] = (claim_s[argr[c]] == j)
                    ? make_int2(argr[c], __float_as_int(urow_s[argr[c]]))
                    : make_int2(0, 0);
    }
    __syncwarp();

    // ---- build free-row list (rows not claimed by any column) ----
    int nfree = 0;
#pragma unroll
    for (int g = 0; g < 4; g++) {
        int row = g * 32 + lane + 1;
        bool fr = (claim_s[row] == SENT);
        unsigned m = __ballot_sync(0xffffffffu, fr);
        int pos = __popc(m & ((1u << lane) - 1));
        if (fr) freerows_s[nfree + pos] = row;
        nfree += __popc(m);
    }
    __syncwarp();

    // ---- SAP phase for free rows (handles arbitrary u) ----
    for (int t = 0; t < nfree; t++) {
        const int   irow  = freerows_s[t];
        const float uinit = urow_s[irow];
        float dist[4] = {INF, INF, INF, INF};
        int   way[4]  = {0, 0, 0, 0};
        bool  used[4] = {false, false, false, false};
        int   i0 = irow;
        float u_i0 = uinit;
        float D  = 0.f;
        int   prevj = 0;
        int   j0;

        for (;;) {
            const float s = D - u_i0;
            uint2 rw = *(const uint2*)(a_s + (i0 - 1) * KN + 4 * lane);
            float2 f01 = __half22float2(*(const __half2*)&rw.x);
            float2 f23 = __half22float2(*(const __half2*)&rw.y);
            float av[4] = { f01.x, f01.y, f23.x, f23.y };

            unsigned bestkey = 0xffffffffu;
#pragma unroll
            for (int c = 0; c < 4; c++) {
                if (!used[c]) {
                    float cur = av[c] + (s - v_r[c]);
                    if (cur < dist[c]) { dist[c] = cur; way[c] = prevj; }
                    unsigned k = (ordkey(dist[c]) & ~127u) | (unsigned)(4 * lane + c);
                    bestkey = min(bestkey, k);
                }
            }
            unsigned mk = redux_min_u32(bestkey);
            D = unordkey(mk);                 // uniform across lanes
            int jg = mk & 127;                // winning column, 0-based
            int j1 = jg + 1;
            prevj = j1;

            int2 pu = pu_s[j1];               // {row, u}, one LDS.64
            bool done = (pu.x == 0);
            if (!done && (jg >> 2) == lane) used[jg & 3] = true;
            if (done) { j0 = j1; break; }
            i0 = pu.x;
            u_i0 = __int_as_float(pu.y);
        }

        // deferred dual updates (old matching; each matched row in exactly 1 col)
#pragma unroll
        for (int c = 0; c < 4; c++) {
            if (used[c]) {
                float dd = D - dist[c];
                v_r[c] -= dd;
                int j = 4 * lane + c + 1;
                pu_s[j].y = __float_as_int(__int_as_float(pu_s[j].y) + dd);
            }
        }
        if (lane == 0) pu_s[0] = make_int2(irow, __float_as_int(uinit + D));
        __syncwarp();

        // augment: shift {row,u} pairs along alternating path
        int jj = j0;
        while (jj != 0) {
            int o = jj - 1;
            int c = o & 3;
            int sel = (c == 0) ? way[0] : (c == 1) ? way[1] : (c == 2) ? way[2] : way[3];
            int jn = __shfl_sync(0xffffffffu, sel, o >> 2);
            if (lane == 0) pu_s[jj] = pu_s[jn];
            __syncwarp();
            jj = jn;
        }
        __syncwarp();
    }

    // ---- epilogue: sum matched cost entries (C = -x.y) in fp32 ----
    float dsum = 0.f;
#pragma unroll
    for (int c = 0; c < 4; c++) {
        int j = 4 * lane + c + 1;          // this column, 1-based
        int row = pu_s[j].x;               // matched row, 1-based
        dsum += __half2float(a_s[(row - 1) * KN + (j - 1)]);
    }
#pragma unroll
    for (int s = 16; s; s >>= 1)
        dsum += __shfl_xor_sync(0xffffffffu, dsum, s);
    if (lane == 0) g_dotC[b] = dsum;
}

// ---------------------------------------------------------------------------
// Kernel 3: combine  (norms + 2*sum(matched C)) / (B*K*D)
// ---------------------------------------------------------------------------
__global__ __launch_bounds__(512) void finalize_kernel(float* __restrict__ out) {
    __shared__ double s[BN];
    int t = threadIdx.x;
    s[t] = g_norm[2 * t] + g_norm[2 * t + 1] + 2.0 * (double)g_dotC[t];
    __syncthreads();
    for (int st = 256; st; st >>= 1) {
        if (t < st) s[t] += s[t + st];
        __syncthreads();
    }
    if (t == 0) out[0] = (float)(s[0] / ((double)BN * KN * DN));
}

// ---------------------------------------------------------------------------
extern "C" void kernel_launch(void* const* d_in, const int* in_sizes, int n_in,
                              void* d_out, int out_size) {
    const float* X = (const float*)d_in[0];   // input
    const float* Y = (const float*)d_in[1];   // target
    float* out = (float*)d_out;

    cost_kernel<<<2 * BN, 256>>>(X, Y);
    hungarian_kernel<<<BN, 32, KN * KN * (int)sizeof(__half)>>>();
    finalize_kernel<<<1, 512>>>(out);
}

// round 14
// speedup vs baseline: 2.1488x; 1.1893x over previous
#include <cuda_runtime.h>
#include <cuda_fp16.h>
#include <cuda_bf16.h>
#include <cstdint>

#define BN 512   // batches
#define KN 128   // points per batch
#define DN 512   // feature dim

// Scratch (static device allocations allowed)
__device__ __half  g_cost[(size_t)BN * KN * KN];   // 16.8 MB, cost = -x.y (fp16)
__device__ double  g_norm[2 * BN];                 // per (batch, n-half) norm sums
__device__ float   g_dotC[BN];                     // per-batch  sum_i C[i, perm(i)]

// ---------------------------------------------------------------------------
// helpers
// ---------------------------------------------------------------------------
__device__ __forceinline__ uint32_t smem_u32(const void* p) {
    return (uint32_t)__cvta_generic_to_shared(p);
}
__device__ __forceinline__ void ldsm_x4(uint32_t& r0, uint32_t& r1,
                                        uint32_t& r2, uint32_t& r3, uint32_t addr) {
    asm volatile("ldmatrix.sync.aligned.m8n8.x4.shared.b16 {%0,%1,%2,%3}, [%4];"
                 : "=r"(r0), "=r"(r1), "=r"(r2), "=r"(r3) : "r"(addr));
}
__device__ __forceinline__ void mma_bf16(float& c0, float& c1, float& c2, float& c3,
                                         uint32_t a0, uint32_t a1, uint32_t a2, uint32_t a3,
                                         uint32_t b0, uint32_t b1) {
    asm volatile("mma.sync.aligned.m16n8k16.row.col.f32.bf16.bf16.f32 "
                 "{%0,%1,%2,%3}, {%4,%5,%6,%7}, {%8,%9}, {%0,%1,%2,%3};"
                 : "+f"(c0), "+f"(c1), "+f"(c2), "+f"(c3)
                 : "r"(a0), "r"(a1), "r"(a2), "r"(a3), "r"(b0), "r"(b1));
}
__device__ __forceinline__ unsigned redux_min_u32(unsigned v) {
    unsigned r;
    asm("redux.sync.min.u32 %0, %1, 0xffffffff;" : "=r"(r) : "r"(v));
    return r;
}
__device__ __forceinline__ unsigned ordkey(float f) {
    unsigned u = __float_as_uint(f);
    return (u & 0x80000000u) ? ~u : (u | 0x80000000u);
}
__device__ __forceinline__ float unordkey(unsigned k) {
    unsigned u = (k & 0x80000000u) ? (k & 0x7fffffffu) : ~k;
    return __uint_as_float(u);
}
__device__ __forceinline__ uint4 pack_bf16x8(float4 f0, float4 f1) {
    uint4 pk;
    { __nv_bfloat162 t = __floats2bfloat162_rn(f0.x, f0.y); pk.x = *(uint32_t*)&t; }
    { __nv_bfloat162 t = __floats2bfloat162_rn(f0.z, f0.w); pk.y = *(uint32_t*)&t; }
    { __nv_bfloat162 t = __floats2bfloat162_rn(f1.x, f1.y); pk.z = *(uint32_t*)&t; }
    { __nv_bfloat162 t = __floats2bfloat162_rn(f1.z, f1.w); pk.w = *(uint32_t*)&t; }
    return pk;
}

// ---------------------------------------------------------------------------
// Kernel 1: C[b][i][j] = -(X[b,i,:] . Y[b,j,:]), bf16 MMA, fp16 output.
// Grid = 1024: (batch, n-half). Each CTA computes 128 x 64 of C with 8 warps
// in a 4(M) x 2(N) grid, warp tile 32x32, acc = 32 regs/thread.
// Software pipeline: registers prefetch k-block kb+1 while MMAs consume kb,
// overlapping the ~600-cycle LDG latency with tensor work.
// Norms: X counted by nh==0 CTA only; each CTA counts its own Y half.
// ---------------------------------------------------------------------------
__device__ __forceinline__ int chunk_off(int row, int c) {   // in 16B units
    return row * 8 + (c ^ (row & 7));
}

__global__ __launch_bounds__(256, 2) void cost_kernel(const float* __restrict__ X,
                                                      const float* __restrict__ Y) {
    __shared__ uint4 Xs[1024];   // 16 KB: 128 rows x 8 chunks
    __shared__ uint4 Ys[512];    //  8 KB:  64 rows x 8 chunks
    __shared__ double nred[256];

    const int b   = blockIdx.x >> 1;
    const int nh  = blockIdx.x & 1;     // which 64-col half of C / rows of Y
    const int tid = threadIdx.x;
    const int w    = tid >> 5;
    const int lane = tid & 31;
    const int wm = w >> 1;       // 0..3  -> m base = wm*32
    const int wn = w & 1;        // 0..1  -> n base = wn*32

    const float* xb = X + (size_t)b * KN * DN;
    const float* yb = Y + (size_t)b * KN * DN + (size_t)nh * 64 * DN;

    float acc[2][4][4];
#pragma unroll
    for (int mt = 0; mt < 2; mt++)
#pragma unroll
        for (int nt = 0; nt < 4; nt++)
#pragma unroll
            for (int q = 0; q < 4; q++) acc[mt][nt][q] = 0.f;

    float nacc = 0.f;

    const uint32_t xs_base = smem_u32(Xs);
    const uint32_t ys_base = smem_u32(Ys);

    // prefetch registers for one k-block (X: 4 chunks, Y: 2 chunks per thread)
    float4 rx[4][2];
    float4 ry[2][2];

    // precomputed per-thread addressing
    const int xrow = tid >> 3;           // X rows handled: xrow, then +32 each qi? no:
    // For X: qi-th chunk index q = tid + 256*qi -> row = q>>3, c = q&7.
    // tid>>3 in 0..31, so rows are xrow + 32*qi; column chunk c constant = tid&7.
    const int cch  = tid & 7;

    // ---- prologue: load k-block 0 ----
#pragma unroll
    for (int qi = 0; qi < 4; qi++) {
        const float* sx = xb + (xrow + 32 * qi) * DN + cch * 8;
        rx[qi][0] = *(const float4*)sx;
        rx[qi][1] = *(const float4*)(sx + 4);
    }
#pragma unroll
    for (int qi = 0; qi < 2; qi++) {
        const float* sy = yb + (xrow + 32 * qi) * DN + cch * 8;
        ry[qi][0] = *(const float4*)sy;
        ry[qi][1] = *(const float4*)(sy + 4);
    }

    for (int kb = 0; kb < 8; kb++) {     // K blocks of 64
        // ---- store the prefetched block to smem (+ norm accumulation) ----
#pragma unroll
        for (int qi = 0; qi < 4; qi++) {
            float4 f0 = rx[qi][0], f1 = rx[qi][1];
            if (nh == 0)
                nacc += f0.x * f0.x + f0.y * f0.y + f0.z * f0.z + f0.w * f0.w
                      + f1.x * f1.x + f1.y * f1.y + f1.z * f1.z + f1.w * f1.w;
            Xs[chunk_off(xrow + 32 * qi, cch)] = pack_bf16x8(f0, f1);
        }
#pragma unroll
        for (int qi = 0; qi < 2; qi++) {
            float4 g0 = ry[qi][0], g1 = ry[qi][1];
            nacc += g0.x * g0.x + g0.y * g0.y + g0.z * g0.z + g0.w * g0.w
                  + g1.x * g1.x + g1.y * g1.y + g1.z * g1.z + g1.w * g1.w;
            Ys[chunk_off(xrow + 32 * qi, cch)] = pack_bf16x8(g0, g1);
        }
        __syncthreads();

        // ---- issue next block's LDGs early (overlap with MMA below) ----
        if (kb < 7) {
            const int koff = (kb + 1) * 64;
#pragma unroll
            for (int qi = 0; qi < 4; qi++) {
                const float* sx = xb + (xrow + 32 * qi) * DN + koff + cch * 8;
                rx[qi][0] = *(const float4*)sx;
                rx[qi][1] = *(const float4*)(sx + 4);
            }
#pragma unroll
            for (int qi = 0; qi < 2; qi++) {
                const float* sy = yb + (xrow + 32 * qi) * DN + koff + cch * 8;
                ry[qi][0] = *(const float4*)sy;
                ry[qi][1] = *(const float4*)(sy + 4);
            }
        }

        // ---- MMA phase on the current smem tiles ----
#pragma unroll
        for (int ks = 0; ks < 4; ks++) {      // k16 steps within block
            const int sub = lane >> 3;
            const int r   = lane & 7;
            uint32_t A[2][4];
#pragma unroll
            for (int mt = 0; mt < 2; mt++) {
                int rowA = wm * 32 + mt * 16 + (sub & 1) * 8 + r;
                int kch  = ks * 2 + (sub >> 1);
                uint32_t ad = xs_base + (uint32_t)(chunk_off(rowA, kch) << 4);
                ldsm_x4(A[mt][0], A[mt][1], A[mt][2], A[mt][3], ad);
            }
            uint32_t Bf[2][4];
#pragma unroll
            for (int g2 = 0; g2 < 2; g2++) {
                int rowB = wn * 32 + g2 * 16 + (sub >> 1) * 8 + r;
                int kch  = ks * 2 + (sub & 1);
                uint32_t ad = ys_base + (uint32_t)(chunk_off(rowB, kch) << 4);
                ldsm_x4(Bf[g2][0], Bf[g2][1], Bf[g2][2], Bf[g2][3], ad);
            }
#pragma unroll
            for (int mt = 0; mt < 2; mt++)
#pragma unroll
                for (int nt = 0; nt < 4; nt++) {
                    int g2 = nt >> 1, h = nt & 1;
                    mma_bf16(acc[mt][nt][0], acc[mt][nt][1], acc[mt][nt][2], acc[mt][nt][3],
                             A[mt][0], A[mt][1], A[mt][2], A[mt][3],
                             Bf[g2][h * 2 + 0], Bf[g2][h * 2 + 1]);
                }
        }
        __syncthreads();
    }

    __half* cb = g_cost + (size_t)b * KN * KN;
    const int g = lane >> 2, t = lane & 3;
#pragma unroll
    for (int mt = 0; mt < 2; mt++)
#pragma unroll
        for (int nt = 0; nt < 4; nt++) {
            int row0 = wm * 32 + mt * 16 + g;
            int col  = nh * 64 + wn * 32 + nt * 8 + 2 * t;
            *(__half2*)(cb + row0 * KN + col) =
                __floats2half2_rn(-acc[mt][nt][0], -acc[mt][nt][1]);
            *(__half2*)(cb + (row0 + 8) * KN + col) =
                __floats2half2_rn(-acc[mt][nt][2], -acc[mt][nt][3]);
        }

    nred[tid] = (double)nacc;
    __syncthreads();
    for (int s = 128; s; s >>= 1) {
        if (tid < s) nred[tid] += nred[tid + s];
        __syncthreads();
    }
    if (tid == 0) g_norm[blockIdx.x] = nred[0];
}

// ---------------------------------------------------------------------------
// Kernel 2: Jonker-Volgenant LAP, one warp/batch, fp16 tile (32 KB).
// Full JV init: ROW reduction (u[i] = row min) then COLUMN reduction
// (v[j] = min_i (a - u)), greedy claim on zero reduced costs, then Dijkstra
// SAP for leftover free rows (supports arbitrary u).
// Epilogue: emit sum_i C[i, perm(i)] (matched fp16 entries, fp32 sum).
// ---------------------------------------------------------------------------
__global__ __launch_bounds__(32) void hungarian_kernel() {
    extern __shared__ __half a_s[];        // 128*128 halfs = 32 KB
    __shared__ int2  pu_s[KN + 1];         // [col] = {row (1-based, 0=free), u_bits}
    __shared__ int   claim_s[KN + 1];      // [row] = claiming column (1-based)
    __shared__ int   freerows_s[KN];
    __shared__ float urow_s[KN + 1];       // [row 1-based] = row reduction u[i]

    const int b = blockIdx.x;
    const int lane = threadIdx.x;
    const float INF = 1e30f;
    const int SENT = 0x7fffffff;

    {   // load cost tile (2048 uint4)
        const uint4* src = (const uint4*)(g_cost + (size_t)b * KN * KN);
        uint4* dst = (uint4*)a_s;
#pragma unroll
        for (int q = 0; q < 64; q++) dst[lane + 32 * q] = src[lane + 32 * q];
    }
    for (int t = lane; t <= KN; t += 32) claim_s[t] = SENT;
    __syncwarp();

    // ---- phase 0: row reduction  u[i] = min_j a[i][j] ----
    for (int r = 0; r < KN; r++) {
        uint2 rw = *(const uint2*)(a_s + r * KN + 4 * lane);
        __half2 h01 = *(const __half2*)&rw.x;
        __half2 h23 = *(const __half2*)&rw.y;
        __half2 m2 = __hmin2(h01, h23);
        float m = fminf(__low2float(m2), __high2float(m2));
        unsigned mk = redux_min_u32(ordkey(m));
        if (lane == 0) urow_s[r + 1] = unordkey(mk);
    }
    __syncwarp();

    // ---- phase 1: column reduction on reduced costs ----
    float v_r[4] = {INF, INF, INF, INF};
    int   argr[4] = {1, 1, 1, 1};
    for (int r = 0; r < KN; r++) {
        float ur = urow_s[r + 1];
        uint2 rw = *(const uint2*)(a_s + r * KN + 4 * lane);
        float2 f01 = __half22float2(*(const __half2*)&rw.x);
        float2 f23 = __half22float2(*(const __half2*)&rw.y);
        float av[4] = { f01.x - ur, f01.y - ur, f23.x - ur, f23.y - ur };
#pragma unroll
        for (int c = 0; c < 4; c++)
            if (av[c] < v_r[c]) { v_r[c] = av[c]; argr[c] = r + 1; }
    }
    // greedy claim: lowest column index wins a contested row
#pragma unroll
    for (int c = 0; c < 4; c++)
        atomicMin(&claim_s[argr[c]], 4 * lane + c + 1);
    __syncwarp();
#pragma unroll
    for (int c = 0; c < 4; c++) {
        int j = 4 * lane + c + 1;
        pu_s[j] = (claim_s[argr[c]] == j)
                    ? make_int2(argr[c], __float_as_int(urow_s[argr[c]]))
                    : make_int2(0, 0);
    }
    __syncwarp();

    // ---- build free-row list (rows not claimed by any column) ----
    int nfree = 0;
#pragma unroll
    for (int g = 0; g < 4; g++) {
        int row = g * 32 + lane + 1;
        bool fr = (claim_s[row] == SENT);
        unsigned m = __ballot_sync(0xffffffffu, fr);
        int pos = __popc(m & ((1u << lane) - 1));
        if (fr) freerows_s[nfree + pos] = row;
        nfree += __popc(m);
    }
    __syncwarp();

    // ---- SAP phase for free rows (handles arbitrary u) ----
    for (int t = 0; t < nfree; t++) {
        const int   irow  = freerows_s[t];
        const float uinit = urow_s[irow];
        float dist[4] = {INF, INF, INF, INF};
        int   way[4]  = {0, 0, 0, 0};
        bool  used[4] = {false, false, false, false};
        int   i0 = irow;
        float u_i0 = uinit;
        float D  = 0.f;
        int   prevj = 0;
        int   j0;

        for (;;) {
            const float s = D - u_i0;
            uint2 rw = *(const uint2*)(a_s + (i0 - 1) * KN + 4 * lane);
            float2 f01 = __half22float2(*(const __half2*)&rw.x);
            float2 f23 = __half22float2(*(const __half2*)&rw.y);
            float av[4] = { f01.x, f01.y, f23.x, f23.y };

            unsigned bestkey = 0xffffffffu;
#pragma unroll
            for (int c = 0; c < 4; c++) {
                if (!used[c]) {
                    float cur = av[c] + (s - v_r[c]);
                    if (cur < dist[c]) { dist[c] = cur; way[c] = prevj; }
                    unsigned k = (ordkey(dist[c]) & ~127u) | (unsigned)(4 * lane + c);
                    bestkey = min(bestkey, k);
                }
            }
            unsigned mk = redux_min_u32(bestkey);
            D = unordkey(mk);                 // uniform across lanes
            int jg = mk & 127;                // winning column, 0-based
            int j1 = jg + 1;
            prevj = j1;

            int2 pu = pu_s[j1];               // {row, u}, one LDS.64
            bool done = (pu.x == 0);
            if (!done && (jg >> 2) == lane) used[jg & 3] = true;
            if (done) { j0 = j1; break; }
            i0 = pu.x;
            u_i0 = __int_as_float(pu.y);
        }

        // deferred dual updates (old matching; each matched row in exactly 1 col)
#pragma unroll
        for (int c = 0; c < 4; c++) {
            if (used[c]) {
                float dd = D - dist[c];
                v_r[c] -= dd;
                int j = 4 * lane + c + 1;
                pu_s[j].y = __float_as_int(__int_as_float(pu_s[j].y) + dd);
            }
        }
        if (lane == 0) pu_s[0] = make_int2(irow, __float_as_int(uinit + D));
        __syncwarp();

        // augment: shift {row,u} pairs along alternating path
        int jj = j0;
        while (jj != 0) {
            int o = jj - 1;
            int c = o & 3;
            int sel = (c == 0) ? way[0] : (c == 1) ? way[1] : (c == 2) ? way[2] : way[3];
            int jn = __shfl_sync(0xffffffffu, sel, o >> 2);
            if (lane == 0) pu_s[jj] = pu_s[jn];
            __syncwarp();
            jj = jn;
        }
        __syncwarp();
    }

    // ---- epilogue: sum matched cost entries (C = -x.y) in fp32 ----
    float dsum = 0.f;
#pragma unroll
    for (int c = 0; c < 4; c++) {
        int j = 4 * lane + c + 1;          // this column, 1-based
        int row = pu_s[j].x;               // matched row, 1-based
        dsum += __half2float(a_s[(row - 1) * KN + (j - 1)]);
    }
#pragma unroll
    for (int s = 16; s; s >>= 1)
        dsum += __shfl_xor_sync(0xffffffffu, dsum, s);
    if (lane == 0) g_dotC[b] = dsum;
}

// ---------------------------------------------------------------------------
// Kernel 3: combine  (norms + 2*sum(matched C)) / (B*K*D)
// ---------------------------------------------------------------------------
__global__ __launch_bounds__(512) void finalize_kernel(float* __restrict__ out) {
    __shared__ double s[BN];
    int t = threadIdx.x;
    s[t] = g_norm[2 * t] + g_norm[2 * t + 1] + 2.0 * (double)g_dotC[t];
    __syncthreads();
    for (int st = 256; st; st >>= 1) {
        if (t < st) s[t] += s[t + st];
        __syncthreads();
    }
    if (t == 0) out[0] = (float)(s[0] / ((double)BN * KN * DN));
}

// ---------------------------------------------------------------------------
extern "C" void kernel_launch(void* const* d_in, const int* in_sizes, int n_in,
                              void* d_out, int out_size) {
    const float* X = (const float*)d_in[0];   // input
    const float* Y = (const float*)d_in[1];   // target
    float* out = (float*)d_out;

    cost_kernel<<<2 * BN, 256>>>(X, Y);
    hungarian_kernel<<<BN, 32, KN * KN * (int)sizeof(__half)>>>();
    finalize_kernel<<<1, 512>>>(out);
}